// round 5
// baseline (speedup 1.0000x reference)
#include <cuda_runtime.h>

#define NB 64
#define SSTR 68              // padded row stride (floats)
#define BUF (NB * SSTR)
#define NT 512               // main kernel threads

static __device__ float g_F[2][NB * NB];   // F_k = P @ Lh_k  (row-major)

// ---------------- f32x2 packed helpers ----------------
__device__ __forceinline__ unsigned long long pk2(float x) {
    unsigned long long r; unsigned u = __float_as_uint(x);
    asm("mov.b64 %0, {%1,%1};" : "=l"(r) : "r"(u));
    return r;
}
__device__ __forceinline__ void fma2(unsigned long long& d,
                                     unsigned long long a, unsigned long long b) {
    asm("fma.rn.f32x2 %0, %1, %2, %3;" : "=l"(d) : "l"(a), "l"(b), "l"(d));
}
__device__ __forceinline__ float2 unpk(unsigned long long v) {
    unsigned lo, hi;
    asm("mov.b64 {%0,%1}, %2;" : "=r"(lo), "=r"(hi) : "l"(v));
    return make_float2(__uint_as_float(lo), __uint_as_float(hi));
}

// ---------------------------------------------------------------------------
// scalar matmul (used only by the tiny precompute kernel; 256-thread mapping)
// ---------------------------------------------------------------------------
template<bool A_TRANS>
__device__ __forceinline__ void do_mm(const float* __restrict__ As,
                                      const float* __restrict__ Bs,
                                      float* __restrict__ Out, int emode)
{
    const int tid = threadIdx.x;
    const int tx4 = (tid & 15) * 4;
    const int ty4 = (tid >> 4) * 4;
    float acc[4][4] = {};
#pragma unroll 4
    for (int k = 0; k < NB; ++k) {
        float a0, a1, a2, a3;
        if (A_TRANS) {
            float4 av = *(const float4*)(As + k * SSTR + ty4);
            a0 = av.x; a1 = av.y; a2 = av.z; a3 = av.w;
        } else {
            a0 = As[(ty4 + 0) * SSTR + k];
            a1 = As[(ty4 + 1) * SSTR + k];
            a2 = As[(ty4 + 2) * SSTR + k];
            a3 = As[(ty4 + 3) * SSTR + k];
        }
        float4 bv = *(const float4*)(Bs + k * SSTR + tx4);
#pragma unroll
        for (int j = 0; j < 4; ++j) {
            float b = (&bv.x)[j];
            acc[0][j] = fmaf(a0, b, acc[0][j]);
            acc[1][j] = fmaf(a1, b, acc[1][j]);
            acc[2][j] = fmaf(a2, b, acc[2][j]);
            acc[3][j] = fmaf(a3, b, acc[3][j]);
        }
    }
    if (emode == 2) {
#pragma unroll
        for (int i = 0; i < 4; ++i)
#pragma unroll
            for (int j = 0; j < 4; ++j)
                Out[(tx4 + j) * SSTR + (ty4 + i)] = acc[i][j];
    } else if (emode == 3) {
#pragma unroll
        for (int i = 0; i < 4; ++i)
            *(float4*)(Out + (ty4 + i) * NB + tx4) =
                make_float4(acc[i][0], acc[i][1], acc[i][2], acc[i][3]);
    } else {
#pragma unroll
        for (int i = 0; i < 4; ++i)
            *(float4*)(Out + (ty4 + i) * SSTR + tx4) =
                make_float4(acc[i][0], acc[i][1], acc[i][2], acc[i][3]);
    }
}

// ---------------------------------------------------------------------------
// packed mm, 4x4 tile: Out(i,j) (+)= sum_k (A[k][i] + sc*A2[k][i]) * MC[k][j]
// A rows ry..ry+3 (one 16B LDS, warp has 2 distinct addrs -> broadcast),
// B cols cx..cx+3 (MC shared by both half-warps -> broadcast).
// ---------------------------------------------------------------------------
template<bool FUSE, bool ACCUM>
__device__ __forceinline__ void mm4x4(const float* __restrict__ As,
                                      const float* __restrict__ A2s,
                                      const float* __restrict__ Bs,
                                      float* __restrict__ Out,
                                      int ry, int cx, float sc)
{
    unsigned long long acc[2][4] = {};   // acc[p][j]: rows (ry+2p, ry+2p+1), col cx+j
    const unsigned long long sc2 = pk2(sc);
#pragma unroll 4
    for (int k = 0; k < NB; ++k) {
        ulonglong2 a01 = *(const ulonglong2*)(As + k * SSTR + ry);
        if (FUSE) {
            ulonglong2 f01 = *(const ulonglong2*)(A2s + k * SSTR + ry);
            fma2(a01.x, sc2, f01.x);
            fma2(a01.y, sc2, f01.y);
        }
        float4 bv = *(const float4*)(Bs + k * SSTR + cx);
        unsigned long long b0 = pk2(bv.x), b1 = pk2(bv.y),
                           b2 = pk2(bv.z), b3 = pk2(bv.w);
        fma2(acc[0][0], a01.x, b0);
        fma2(acc[0][1], a01.x, b1);
        fma2(acc[0][2], a01.x, b2);
        fma2(acc[0][3], a01.x, b3);
        fma2(acc[1][0], a01.y, b0);
        fma2(acc[1][1], a01.y, b1);
        fma2(acc[1][2], a01.y, b2);
        fma2(acc[1][3], a01.y, b3);
    }
#pragma unroll
    for (int p = 0; p < 2; ++p) {
        float2 c0 = unpk(acc[p][0]);
        float2 c1 = unpk(acc[p][1]);
        float2 c2 = unpk(acc[p][2]);
        float2 c3 = unpk(acc[p][3]);
        float4 vlo = make_float4(c0.x, c1.x, c2.x, c3.x);   // row ry+2p
        float4 vhi = make_float4(c0.y, c1.y, c2.y, c3.y);   // row ry+2p+1
        float4* plo = (float4*)(Out + (ry + 2 * p + 0) * SSTR + cx);
        float4* phi = (float4*)(Out + (ry + 2 * p + 1) * SSTR + cx);
        if (ACCUM) {
            float4 o0 = *plo, o1 = *phi;
            vlo.x += o0.x; vlo.y += o0.y; vlo.z += o0.z; vlo.w += o0.w;
            vhi.x += o1.x; vhi.y += o1.y; vhi.z += o1.z; vhi.w += o1.w;
        }
        *plo = vlo; *phi = vhi;
    }
}

// copy 64x64 row-major global -> smem (stride SSTR), coalesced float4 (any blockDim)
__device__ __forceinline__ void load_rm(float* __restrict__ dst,
                                        const float* __restrict__ g,
                                        int tid, int nthr)
{
    for (int e = tid * 4; e < NB * NB; e += nthr * 4)
        *(float4*)(dst + (e >> 6) * SSTR + (e & 63)) = *(const float4*)(g + e);
}

// split constant stage: LDG transposed gather into regs, then STS later
struct ConstRegs { float v[2][4]; };

__device__ __forceinline__ void ldgT(ConstRegs& cr, const float* __restrict__ gM,
                                     int tid)
{
#pragma unroll
    for (int it = 0; it < 2; ++it) {
        int idx = it * NT + tid;           // 0..1023
        int k  = idx & 63;
        int i4 = (idx >> 6) << 2;
#pragma unroll
        for (int r = 0; r < 4; ++r)
            cr.v[it][r] = gM[(i4 + r) * NB + k];
    }
}
__device__ __forceinline__ void stsT(const ConstRegs& cr, float* __restrict__ MC,
                                     int tid)
{
#pragma unroll
    for (int it = 0; it < 2; ++it) {
        int idx = it * NT + tid;
        int k  = idx & 63;
        int i4 = (idx >> 6) << 2;
        *(float4*)(MC + k * SSTR + i4) =
            make_float4(cr.v[it][0], cr.v[it][1], cr.v[it][2], cr.v[it][3]);
    }
}

// 256-thread transposed stage for krk_pre
__device__ __forceinline__ void load_const_T256(float* __restrict__ MC,
                                                const float* __restrict__ gM, int tid)
{
#pragma unroll
    for (int it = 0; it < 4; ++it) {
        int idx = it * 256 + tid;
        int k  = idx & 63;
        int i4 = (idx >> 6) << 2;
        float v0 = gM[(i4 + 0) * NB + k];
        float v1 = gM[(i4 + 1) * NB + k];
        float v2 = gM[(i4 + 2) * NB + k];
        float v3 = gM[(i4 + 3) * NB + k];
        *(float4*)(MC + k * SSTR + i4) = make_float4(v0, v1, v2, v3);
    }
}

// ---------------------------------------------------------------------------
// precompute kernel: P = U_one @ (I + W + W^2), W = I - U_half ; F_k = P @ Lh_k
// ---------------------------------------------------------------------------
__global__ void __launch_bounds__(256, 1)
krk_pre(const float* __restrict__ U_half,
        const float* __restrict__ U_one,
        const float* __restrict__ Lh)
{
    extern __shared__ float sm[];
    float* Wt = sm;
    float* Wr = sm + BUF;
    float* Cc = sm + 2 * BUF;
    const int tid = threadIdx.x;

    for (int e = tid; e < NB * NB; e += 256) {
        int i = e >> 6, j = e & 63;
        float w = ((i == j) ? 1.f : 0.f) - U_half[e];
        Wr[i * SSTR + j] = w;
        Wt[j * SSTR + i] = w;
    }
    __syncthreads();
    do_mm<true>(Wt, Wr, Cc, 0);                        // Cc = W @ W
    __syncthreads();
    for (int e = tid; e < NB * NB; e += 256) {
        int i = e >> 6, j = e & 63;
        int idx = i * SSTR + j;
        Wr[idx] = ((i == j) ? 1.f : 0.f) + Wr[idx] + Cc[idx];   // Winv
        Wt[j * SSTR + i] = U_one[e];                            // U_one^T
    }
    __syncthreads();
    do_mm<true>(Wt, Wr, Cc, 2);                        // Cc = P^T
    __syncthreads();
    for (int kk = 0; kk < 2; ++kk) {
        load_rm(Wr, Lh + kk * NB * NB, tid, 256);
        __syncthreads();
        do_mm<true>(Cc, Wr, &g_F[kk][0], 3);           // g_F[kk] = P @ Lh_k
        __syncthreads();
    }
}

// ---------------------------------------------------------------------------
// main kernel: 512 threads, 2 matrices per CTA, double-buffered constants
// per-matrix buffers: [R0, TAt, BD, ST, SB] ; MC0/MC1 shared
// ---------------------------------------------------------------------------
__global__ void __launch_bounds__(NT, 1)
krk_main(const float* __restrict__ rho0,
         const float* __restrict__ U_half,
         const float* __restrict__ U_one,
         const float* __restrict__ L0,
         const float* __restrict__ L1,
         float* __restrict__ out)
{
    extern __shared__ float sm[];
    const int tid = threadIdx.x;
    const int w = tid >> 5, l = tid & 31;
    const int h = l >> 4, lp = l & 15;      // half-warp selects matrix
    const int ry = w << 2;                  // 4-row block (16 warps x 4 = 64 rows)
    const int cx = lp << 2;                 // 4-col block
    float* mb = sm + h * 5 * BUF;
    float* MCbuf[2] = { sm + 10 * BUF, sm + 11 * BUF };
    const int b = blockIdx.x;
    const float dt = 0.01f;

    for (int m = 0; m < 2; ++m)
        load_rm(sm + m * 5 * BUF, rho0 + (2 * b + m) * (NB * NB), tid, NT);

    // buffer indices: 0=R0, 1=TAt, 2=BD, 3=ST, 4=SB
    const float* cptr[9] = { L0, L0 + NB * NB, U_half, U_one, U_one,
                             &g_F[0][0], &g_F[1][0], L1, L1 + NB * NB };
    const int xi[9] = { 0, 0, 0, 0, 2, 3, 3, 3, 3 };
    const int oi[9] = { 2, 2, 3, 4, 0, 2, 2, 2, 2 };
    const int em[9] = { 0, 1, 0, 0, 0, 0, 1, 0, 1 };

    // preload constant for stage 0
    {
        ConstRegs cr;
        ldgT(cr, cptr[0], tid);
        stsT(cr, MCbuf[0], tid);
    }
    __syncthreads();

    for (int s = 0; s < 9; ++s) {
        float* MC  = MCbuf[s & 1];
        float* MCn = MCbuf[(s + 1) & 1];
        const float* As = mb + xi[s] * BUF;
        float* TAt = mb + BUF;

        ConstRegs cr;
        if (s + 1 < 9) ldgT(cr, cptr[s + 1], tid);     // overlap L2 latency w/ mm1

        // mm1: TAt[i][j] = sum_k X[k][i] * M[j][k] = (M@X)^T[i][j]
        if (s == 2)
            mm4x4<true, false>(As, mb + 2 * BUF, MC, TAt, ry, cx, 0.5f * dt);
        else
            mm4x4<false, false>(As, nullptr, MC, TAt, ry, cx, 0.f);

        if (s + 1 < 9) stsT(cr, MCn, tid);             // safe: MCn idle this stage
        __syncthreads();

        // mm2: Out[i][j] (+)= sum_k TAt[k][i] * M[j][k] = (M@X@M^T)[i][j]
        float* Ob = mb + oi[s] * BUF;
        if (em[s]) mm4x4<false, true>(TAt, nullptr, MC, Ob, ry, cx, 0.f);
        else       mm4x4<false, false>(TAt, nullptr, MC, Ob, ry, cx, 0.f);
        __syncthreads();

        if (s == 6) {
            // rho2 = S + dt*PDP -> ST ; out-partial = S + dt/6*T + 2dt/3*PDP -> SB
            const float c1 = dt / 6.0f, c2 = 2.0f * dt / 3.0f;
            for (int m = 0; m < 2; ++m) {
                float* R0m = sm + m * 5 * BUF;          // holds T
                float* BDm = R0m + 2 * BUF;             // PDP
                float* STm = R0m + 3 * BUF;
                float* SBm = R0m + 4 * BUF;             // S
                for (int e = tid * 4; e < NB * NB; e += NT * 4) {
                    int idx = (e >> 6) * SSTR + (e & 63);
                    float4 sv = *(float4*)(SBm + idx);
                    float4 dv = *(float4*)(BDm + idx);
                    float4 tv = *(float4*)(R0m + idx);
                    float4 r2, ob;
                    r2.x = fmaf(dt, dv.x, sv.x);
                    r2.y = fmaf(dt, dv.y, sv.y);
                    r2.z = fmaf(dt, dv.z, sv.z);
                    r2.w = fmaf(dt, dv.w, sv.w);
                    ob.x = sv.x + c1 * tv.x + c2 * dv.x;
                    ob.y = sv.y + c1 * tv.y + c2 * dv.y;
                    ob.z = sv.z + c1 * tv.z + c2 * dv.z;
                    ob.w = sv.w + c1 * tv.w + c2 * dv.w;
                    *(float4*)(STm + idx) = r2;
                    *(float4*)(SBm + idx) = ob;
                }
            }
            __syncthreads();
        }
    }

    // final: out = SB + dt/6 * D1(BD)
    {
        const float c1 = dt / 6.0f;
        for (int m = 0; m < 2; ++m) {
            float* BDm = sm + m * 5 * BUF + 2 * BUF;
            float* SBm = sm + m * 5 * BUF + 4 * BUF;
            float* og = out + (2 * b + m) * (NB * NB);
            for (int e = tid * 4; e < NB * NB; e += NT * 4) {
                int idx = (e >> 6) * SSTR + (e & 63);
                float4 sv = *(float4*)(SBm + idx);
                float4 dv = *(float4*)(BDm + idx);
                float4 o;
                o.x = fmaf(c1, dv.x, sv.x);
                o.y = fmaf(c1, dv.y, sv.y);
                o.z = fmaf(c1, dv.z, sv.z);
                o.w = fmaf(c1, dv.w, sv.w);
                *(float4*)(og + e) = o;
            }
        }
    }
}

extern "C" void kernel_launch(void* const* d_in, const int* in_sizes, int n_in,
                              void* d_out, int out_size)
{
    const float* rho0   = (const float*)d_in[0];
    const float* U_half = (const float*)d_in[1];
    const float* U_one  = (const float*)d_in[2];
    const float* L0     = (const float*)d_in[3];
    const float* Lh     = (const float*)d_in[4];
    const float* L1     = (const float*)d_in[5];
    float* out = (float*)d_out;

    const int Bn = in_sizes[0] / (NB * NB);

    cudaFuncSetAttribute(krk_pre,  cudaFuncAttributeMaxDynamicSharedMemorySize, 3 * BUF * 4);
    cudaFuncSetAttribute(krk_main, cudaFuncAttributeMaxDynamicSharedMemorySize, 12 * BUF * 4);

    krk_pre<<<1, 256, 3 * BUF * 4>>>(U_half, U_one, Lh);
    krk_main<<<Bn / 2, NT, 12 * BUF * 4>>>(rho0, U_half, U_one, L0, L1, out);
}